// round 3
// baseline (speedup 1.0000x reference)
#include <cuda_runtime.h>

// ---------------------------------------------------------------------------
// MoE gate: logits = X @ W^T  (fp32 SGEMM), then sigmoid + grouped top-k gate.
// X: [T=16384, 4096] fp32, W: [256, 4096] fp32, bias: [256] fp32.
// out (float32): [0 .. T*8)   = topk_idx   (as float)
//                [T*8..2*T*8) = topk_weight (normalized * 2.5)
// ---------------------------------------------------------------------------

#define KDIM   4096
#define NEXP   256
#define TMAX   16384

#define BM 128
#define BN 128
#define BK 16

__device__ __align__(16) float g_logits[(size_t)TMAX * NEXP];

__global__ __launch_bounds__(256, 2)
void gemm_kernel(const float* __restrict__ X, const float* __restrict__ W)
{
    __shared__ __align__(16) float As[2][BK][BM + 4];
    __shared__ __align__(16) float Bs[2][BK][BN + 4];

    const int tid = threadIdx.x;
    const int m0  = blockIdx.y * BM;
    const int n0  = blockIdx.x * BN;
    const int tx  = tid & 15;   // 0..15 -> N
    const int ty  = tid >> 4;   // 0..15 -> M

    float acc[8][8];
#pragma unroll
    for (int i = 0; i < 8; i++)
#pragma unroll
        for (int j = 0; j < 8; j++) acc[i][j] = 0.0f;

    float4 ra[2], rb[2];

    // ---- fetch stage k0 into registers ----
#define FETCH(k0)                                                            \
    {                                                                        \
        _Pragma("unroll")                                                    \
        for (int i = 0; i < 2; i++) {                                        \
            int idx = tid + i * 256;        /* 0..511 */                     \
            int row = idx >> 2;                                              \
            int c   = idx & 3;                                               \
            ra[i] = *reinterpret_cast<const float4*>(                        \
                X + (size_t)(m0 + row) * KDIM + (k0) + c * 4);               \
            rb[i] = *reinterpret_cast<const float4*>(                        \
                W + (size_t)(n0 + row) * KDIM + (k0) + c * 4);               \
        }                                                                    \
    }

    // ---- store registers into smem buffer b ----
#define STORE(b)                                                             \
    {                                                                        \
        _Pragma("unroll")                                                    \
        for (int i = 0; i < 2; i++) {                                        \
            int idx = tid + i * 256;                                         \
            int row = idx >> 2;                                              \
            int c   = idx & 3;                                               \
            As[b][c * 4 + 0][row] = ra[i].x;                                 \
            As[b][c * 4 + 1][row] = ra[i].y;                                 \
            As[b][c * 4 + 2][row] = ra[i].z;                                 \
            As[b][c * 4 + 3][row] = ra[i].w;                                 \
            Bs[b][c * 4 + 0][row] = rb[i].x;                                 \
            Bs[b][c * 4 + 1][row] = rb[i].y;                                 \
            Bs[b][c * 4 + 2][row] = rb[i].z;                                 \
            Bs[b][c * 4 + 3][row] = rb[i].w;                                 \
        }                                                                    \
    }

    FETCH(0);
    STORE(0);
    __syncthreads();

    int buf = 0;
    const int NSTAGE = KDIM / BK;  // 256
    for (int s = 0; s < NSTAGE; s++) {
        if (s + 1 < NSTAGE) FETCH((s + 1) * BK);

#pragma unroll
        for (int kk = 0; kk < BK; kk++) {
            float a[8], b[8];
            // two float4 stripes per fragment: columns {q*4 .. q*4+3, 64+q*4 ..}
            float4 a0 = *reinterpret_cast<const float4*>(&As[buf][kk][ty * 4]);
            float4 a1 = *reinterpret_cast<const float4*>(&As[buf][kk][64 + ty * 4]);
            float4 b0 = *reinterpret_cast<const float4*>(&Bs[buf][kk][tx * 4]);
            float4 b1 = *reinterpret_cast<const float4*>(&Bs[buf][kk][64 + tx * 4]);
            a[0]=a0.x; a[1]=a0.y; a[2]=a0.z; a[3]=a0.w;
            a[4]=a1.x; a[5]=a1.y; a[6]=a1.z; a[7]=a1.w;
            b[0]=b0.x; b[1]=b0.y; b[2]=b0.z; b[3]=b0.w;
            b[4]=b1.x; b[5]=b1.y; b[6]=b1.z; b[7]=b1.w;
#pragma unroll
            for (int i = 0; i < 8; i++)
#pragma unroll
                for (int j = 0; j < 8; j++)
                    acc[i][j] += a[i] * b[j];
        }

        if (s + 1 < NSTAGE) STORE(buf ^ 1);
        __syncthreads();
        buf ^= 1;
    }

    // epilogue: write logits tile
    const int rbase[2] = {ty * 4, 64 + ty * 4};
    const int cbase[2] = {tx * 4, 64 + tx * 4};
#pragma unroll
    for (int ii = 0; ii < 2; ii++)
#pragma unroll
        for (int i2 = 0; i2 < 4; i2++) {
            int m = m0 + rbase[ii] + i2;
#pragma unroll
            for (int jj = 0; jj < 2; jj++) {
                float4 v;
                v.x = acc[ii * 4 + i2][jj * 4 + 0];
                v.y = acc[ii * 4 + i2][jj * 4 + 1];
                v.z = acc[ii * 4 + i2][jj * 4 + 2];
                v.w = acc[ii * 4 + i2][jj * 4 + 3];
                *reinterpret_cast<float4*>(
                    &g_logits[(size_t)m * NEXP + n0 + cbase[jj]]) = v;
            }
        }
#undef FETCH
#undef STORE
}

// ---------------------------------------------------------------------------
// Gating: one warp per token. Lane l holds experts e = 32*j + l for j=0..7
// (register slot j == group j). Exactly reproduces jax.lax.top_k tie-breaking
// (lower index wins on equal values).
// ---------------------------------------------------------------------------
__global__ void gate_kernel(const float* __restrict__ bias,
                            float* __restrict__ out, int T)
{
    const int gw   = (int)((blockIdx.x * blockDim.x + threadIdx.x) >> 5);
    const int lane = threadIdx.x & 31;
    if (gw >= T) return;

    const float* lg = g_logits + (size_t)gw * NEXP;
    const unsigned FULL = 0xffffffffu;

    float s[8], v[8];
#pragma unroll
    for (int j = 0; j < 8; j++) {
        float x  = lg[j * 32 + lane];
        float sc = 1.0f / (1.0f + expf(-x));   // sigmoid
        s[j] = sc;
        v[j] = sc + bias[j * 32 + lane];       // scores_for_choice
    }

    // group score = sum of top-2 scores_for_choice within the group's 32 lanes
    float gs[8];
#pragma unroll
    for (int j = 0; j < 8; j++) {
        float m1 = v[j], m2 = -3.402823e38f;
#pragma unroll
        for (int off = 16; off > 0; off >>= 1) {
            float o1 = __shfl_xor_sync(FULL, m1, off);
            float o2 = __shfl_xor_sync(FULL, m2, off);
            float nm1 = fmaxf(m1, o1);
            float nm2 = fmaxf(fminf(m1, o1), fmaxf(m2, o2));
            m1 = nm1; m2 = nm2;
        }
        gs[j] = m1 + m2;
    }

    // stable top-4 group selection (ties -> lower group index)
    unsigned sel = 0;
#pragma unroll
    for (int j = 0; j < 8; j++) {
        int rank = 0;
#pragma unroll
        for (int j2 = 0; j2 < 8; j2++)
            rank += (gs[j2] > gs[j]) || (gs[j2] == gs[j] && j2 < j);
        if (rank < 4) sel |= (1u << j);
    }

    float tmp[8];
#pragma unroll
    for (int j = 0; j < 8; j++)
        tmp[j] = ((sel >> j) & 1u) ? v[j] : 0.0f;

    float my_w = 0.0f, wsum = 0.0f;
    int   my_e = 0;
#pragma unroll
    for (int slot = 0; slot < 8; slot++) {
        // local best among my 8 candidates (ascending e within lane,
        // strict > keeps the lowest index on ties)
        float bv = -3.402823e38f;
        int   be = 1 << 20;
#pragma unroll
        for (int j = 0; j < 8; j++) {
            if (tmp[j] > bv) { bv = tmp[j]; be = j * 32 + lane; }
        }
        // warp argmax, tie -> lower expert index
#pragma unroll
        for (int off = 16; off > 0; off >>= 1) {
            float ov = __shfl_xor_sync(FULL, bv, off);
            int   oe = __shfl_xor_sync(FULL, be, off);
            if (ov > bv || (ov == bv && oe < be)) { bv = ov; be = oe; }
        }
        const int jwin = be >> 5, lwin = be & 31;
        // raw sigmoid score of the winner (jwin is warp-uniform)
        float sv_local = s[0];
#pragma unroll
        for (int j = 1; j < 8; j++)
            if (j == jwin) sv_local = s[j];
        float sv = __shfl_sync(FULL, sv_local, lwin);

        wsum += sv;
        if (lane == slot) { my_e = be; my_w = sv; }
        if (lane == lwin) {
#pragma unroll
            for (int j = 0; j < 8; j++)
                if (j == jwin) tmp[j] = -3.402823e38f;
        }
    }

    if (lane < 8) {
        out[(size_t)gw * 8 + lane] = (float)my_e;
        out[(size_t)T * 8 + (size_t)gw * 8 + lane] =
            my_w / (wsum + 1e-20f) * 2.5f;
    }
}

extern "C" void kernel_launch(void* const* d_in, const int* in_sizes, int n_in,
                              void* d_out, int out_size)
{
    const float* hs   = (const float*)d_in[0];  // hidden_states [4,4096,4096]
    const float* w    = (const float*)d_in[1];  // weight [256,4096]
    const float* bias = (const float*)d_in[2];  // e_score_correction_bias [256]
    float* out = (float*)d_out;

    const int T = in_sizes[0] / KDIM;           // 16384

    dim3 g1(NEXP / BN, T / BM);                 // (2, 128)
    gemm_kernel<<<g1, 256>>>(hs, w);

    const int blocks = (T * 32 + 255) / 256;    // 8 warps (tokens) per block
    gate_kernel<<<blocks, 256>>>(bias, out, T);
}